// round 1
// baseline (speedup 1.0000x reference)
#include <cuda_runtime.h>
#include <cuda_bf16.h>
#include <float.h>

// Problem constants (fixed by the reference)
#define BB 16
#define TT 1024
#define VV 4096
#define SS 256
#define NEGV (-1e30f)

// Scratch: lp[b][t][s] = logits[b,t,targets[b,s]] - lse[b,t]   (16 MB)
__device__ float g_lp[(size_t)BB * TT * SS];

// ---------------------------------------------------------------------------
// Kernel 1: per-(b,t) row logsumexp + gather of 256 target columns.
// One block of 256 threads per row. Row staged in smem for the gather.
// ---------------------------------------------------------------------------
__global__ __launch_bounds__(256) void lse_gather_kernel(
    const float* __restrict__ logits,
    const int* __restrict__ targets)
{
    const int row = blockIdx.x;          // row = b*TT + t
    const int b   = row >> 10;           // TT = 1024
    const int tid = threadIdx.x;

    __shared__ float srow[VV];           // 16 KB
    __shared__ float red[16];

    const float4* rp = reinterpret_cast<const float4*>(logits + (size_t)row * VV);

    // Load 16 floats per thread (4x float4), stage into smem, local max.
    float4 v0 = rp[tid];
    float4 v1 = rp[tid + 256];
    float4 v2 = rp[tid + 512];
    float4 v3 = rp[tid + 768];
    float4* s4 = reinterpret_cast<float4*>(srow);
    s4[tid]       = v0;
    s4[tid + 256] = v1;
    s4[tid + 512] = v2;
    s4[tid + 768] = v3;

    float mx = fmaxf(fmaxf(v0.x, v0.y), fmaxf(v0.z, v0.w));
    mx = fmaxf(mx, fmaxf(fmaxf(v1.x, v1.y), fmaxf(v1.z, v1.w)));
    mx = fmaxf(mx, fmaxf(fmaxf(v2.x, v2.y), fmaxf(v2.z, v2.w)));
    mx = fmaxf(mx, fmaxf(fmaxf(v3.x, v3.y), fmaxf(v3.z, v3.w)));

    // Warp reduce max
    #pragma unroll
    for (int o = 16; o > 0; o >>= 1)
        mx = fmaxf(mx, __shfl_xor_sync(0xFFFFFFFFu, mx, o));
    if ((tid & 31) == 0) red[tid >> 5] = mx;
    __syncthreads();
    float m = red[0];
    #pragma unroll
    for (int i = 1; i < 8; i++) m = fmaxf(m, red[i]);

    // Sum of exp(x - m)
    float sum = 0.0f;
    sum += __expf(v0.x - m) + __expf(v0.y - m) + __expf(v0.z - m) + __expf(v0.w - m);
    sum += __expf(v1.x - m) + __expf(v1.y - m) + __expf(v1.z - m) + __expf(v1.w - m);
    sum += __expf(v2.x - m) + __expf(v2.y - m) + __expf(v2.z - m) + __expf(v2.w - m);
    sum += __expf(v3.x - m) + __expf(v3.y - m) + __expf(v3.z - m) + __expf(v3.w - m);
    #pragma unroll
    for (int o = 16; o > 0; o >>= 1)
        sum += __shfl_xor_sync(0xFFFFFFFFu, sum, o);
    if ((tid & 31) == 0) red[8 + (tid >> 5)] = sum;
    __syncthreads();
    float tot = red[8];
    #pragma unroll
    for (int i = 1; i < 8; i++) tot += red[8 + i];

    const float lse = m + __logf(tot);

    // Gather: lp[row][s] = srow[targets[b][s]] - lse
    const int tgt = targets[b * SS + tid];
    g_lp[(size_t)row * SS + tid] = srow[tgt] - lse;
}

// logaddexp, NaN-free at -1e30 sentinels
__device__ __forceinline__ float laexp(float a, float b)
{
    float m = fmaxf(a, b);
    float d = fminf(a, b) - m;           // <= 0
    return m + __logf(1.0f + __expf(d));
}

// ---------------------------------------------------------------------------
// Kernel 2: serial scan over T. One block per batch, thread s owns alpha[s].
// Double-buffered smem provides alpha[s-1]; one __syncthreads per step.
// lp prefetched 8 steps ahead in a register ring.
// ---------------------------------------------------------------------------
__global__ __launch_bounds__(SS) void scan_kernel(
    const int* __restrict__ logits_lengths,
    const int* __restrict__ targets_lengths,
    float* __restrict__ out)
{
    const int b = blockIdx.x;
    const int s = threadIdx.x;
    const int L  = logits_lengths[b];
    const int tl = targets_lengths[b];

    __shared__ float sh[2][SS + 1];

    float alpha = NEGV;
    sh[0][s + 1] = NEGV;
    if (s == 0) { sh[0][0] = 0.0f; sh[1][0] = NEGV; }
    __syncthreads();

    const float* lp = g_lp + (size_t)b * TT * SS + s;

    float pre[8];
    #pragma unroll
    for (int j = 0; j < 8; j++) pre[j] = lp[j * SS];

    int cur = 0;
    for (int tc = 0; tc < TT; tc += 8) {
        float nxt[8];
        if (tc + 8 < TT) {
            #pragma unroll
            for (int j = 0; j < 8; j++) nxt[j] = lp[(tc + 8 + j) * SS];
        }
        #pragma unroll
        for (int j = 0; j < 8; j++) {
            const int t = tc + j;
            const float shifted = sh[cur][s];            // alpha_t[s-1] (or start)
            const float nv = pre[j] + laexp(alpha, shifted);
            if (t < L) alpha = nv;                       // freeze past seq end
            sh[cur ^ 1][s + 1] = alpha;
            if (s == 0) sh[cur ^ 1][0] = NEGV;           // start state only at t==0
            __syncthreads();
            cur ^= 1;
        }
        #pragma unroll
        for (int j = 0; j < 8; j++) pre[j] = nxt[j];
    }

    if (s == tl - 1) atomicAdd(out, -alpha);
}

// ---------------------------------------------------------------------------
extern "C" void kernel_launch(void* const* d_in, const int* in_sizes, int n_in,
                              void* d_out, int out_size)
{
    const float* logits          = (const float*)d_in[0];
    const int*   targets         = (const int*)d_in[1];
    const int*   logits_lengths  = (const int*)d_in[2];
    const int*   targets_lengths = (const int*)d_in[3];
    float*       out             = (float*)d_out;

    cudaMemsetAsync(out, 0, (size_t)out_size * sizeof(float));

    lse_gather_kernel<<<BB * TT, 256>>>(logits, targets);
    scan_kernel<<<BB, SS>>>(logits_lengths, targets_lengths, out);
}